// round 13
// baseline (speedup 1.0000x reference)
#include <cuda_runtime.h>
#include <cuda_bf16.h>
#include <math.h>

#define Bz   2
#define Cc   512
#define Tt   16
#define HWp  1024
#define EPS  1e-5f
#define SCALE 0.04419417382415922f  // 512^-0.5
#define FULLMASK 0xffffffffu
#define SSTR 68     // fp32 score row stride
#define WST  36     // packed weight row stride (uints)

typedef unsigned int uint;

// ---------------- helpers ----------------
__device__ __forceinline__ uint packbf(float lo, float hi) {
    uint r; asm("cvt.rn.bf16x2.f32 %0, %1, %2;" : "=r"(r) : "f"(hi), "f"(lo)); return r;
}
__device__ __forceinline__ void mma_bf16(float4& d, uint a0, uint a1, uint a2, uint a3,
                                         uint b0, uint b1) {
    asm volatile("mma.sync.aligned.m16n8k16.row.col.f32.bf16.bf16.f32 "
                 "{%0,%1,%2,%3}, {%4,%5,%6,%7}, {%8,%9}, {%0,%1,%2,%3};"
                 : "+f"(d.x), "+f"(d.y), "+f"(d.z), "+f"(d.w)
                 : "r"(a0), "r"(a1), "r"(a2), "r"(a3), "r"(b0), "r"(b1));
}

// ---------------- scratch ----------------
__device__ float  g_mu  [Bz * 32 * Tt];
__device__ float  g_rstd[Bz * 32 * Tt];
__device__ float  g_kv  [128 * 1024];     // [b*64+s][2C]
__device__ float4 g_kf32[16384];          // score B frags fp32: [b][st(8)][k8(32)][lane(32)]
__device__ float4 g_vf32[16384];          // combine B frags fp32: [b][k8s(4)][ct(64)][lane(32)]
__device__ float  g_ksb [128];

// fragment index maps (must match attn's B-fragment consumption; derived from
// the previously-verified cvt_kernel mapping)
__device__ __forceinline__ int kf_idx(int m, int n) {
    // m = s row (0..127), n = c (0..511); returns float index into (float*)g_kf32
    int b = m >> 6, sr = m & 63;
    int st = sr >> 3, grp = sr & 7;
    int k8 = n >> 4, off = n & 15;
    int reg, tig;
    if (off < 8) { tig = off >> 1; reg = off & 1; }
    else         { tig = (off - 8) >> 1; reg = 2 + (off & 1); }
    return ((((b * 8 + st) * 32 + k8) * 32) + grp * 4 + tig) * 4 + reg;
}
__device__ __forceinline__ int vf_idx(int m, int n) {
    // m = s row (0..127), n = c (0..511); returns float index into (float*)g_vf32
    int b = m >> 6, r = m & 63;
    int k8s = r >> 4, rr = r & 15;
    int reg, tig;
    if (rr < 8) { tig = rr >> 1; reg = rr & 1; }
    else        { tig = (rr - 8) >> 1; reg = 2 + (rr & 1); }
    int ct = n >> 3, grp = n & 7;
    return ((((b * 4 + k8s) * 64) + ct) * 32 + grp * 4 + tig) * 4 + reg;
}

// ---------------- seed: g_kv = bkv bcast, g_kf32 = 0, g_vf32 = 0 ----------------
__global__ void seed_kernel(const float* __restrict__ bkv) {
    int i4 = (blockIdx.x * 256 + threadIdx.x) * 4;   // 0..262140
    if (i4 < 131072) {
        float4 bv = *(const float4*)&bkv[i4 & 1023];
        *(float4*)&g_kv[i4] = bv;
    } else if (i4 < 196608) {
        ((float4*)g_kf32)[(i4 - 131072) >> 2] = make_float4(0.f, 0.f, 0.f, 0.f);
    } else {
        ((float4*)g_vf32)[(i4 - 196608) >> 2] = make_float4(0.f, 0.f, 0.f, 0.f);
    }
}

// ---------------- pre1: kv gemm (blocks 0-255) + gn stats (blocks 256-1279) ----------------
__global__ void pre1_kernel(const float* __restrict__ x, const float* __restrict__ context,
                            const float* __restrict__ wkv) {
    int bid = blockIdx.x;
    int tid = threadIdx.x;

    if (bid >= 256) {     // ---- groupnorm stats ----
        int idx = bid - 256;                 // b*512 + g*16 + t
        int b = idx >> 9, g = (idx >> 4) & 31, t = idx & 15;
        float s = 0.f, sq = 0.f;
        for (int ci = 0; ci < 16; ci++) {
            const float4* row = (const float4*)(x + (size_t)(((b*Cc + g*16 + ci)*Tt + t)) * HWp);
            float4 v = row[tid];
            s  += v.x + v.y + v.z + v.w;
            sq += v.x*v.x + v.y*v.y + v.z*v.z + v.w*v.w;
        }
        __shared__ float s1[256], s2[256];
        s1[tid] = s; s2[tid] = sq;
        __syncthreads();
        for (int st = 128; st > 0; st >>= 1) {
            if (tid < st) { s1[tid] += s1[tid + st]; s2[tid] += s2[tid + st]; }
            __syncthreads();
        }
        if (tid == 0) {
            const float invN = 1.f / 16384.f;
            float mu  = s1[0] * invN;
            float var = s2[0] * invN - mu * mu;
            g_mu[idx] = mu;
            g_rstd[idx] = rsqrtf(var + EPS);
        }
        return;
    }

    // ---- kv = context @ wkv^T (split-K 8, atomic into seeded g_kv) ----
    __shared__ float As[16][68];
    __shared__ float Bs[16][68];
    int n0 = (bid & 15) * 64;
    int m0 = ((bid >> 4) & 1) * 64;
    int k0base = (bid >> 5) * 128;
    int tx = tid & 15, ty = tid >> 4;

    float acc[4][4];
    #pragma unroll
    for (int i = 0; i < 4; i++)
        #pragma unroll
        for (int j = 0; j < 4; j++) acc[i][j] = 0.f;

    for (int k0 = k0base; k0 < k0base + 128; k0 += 16) {
        {
            int mm = tid >> 2, kb = (tid & 3) << 2;
            float4 av = *(const float4*)&context[(size_t)(m0 + mm) * 1024 + k0 + kb];
            As[kb+0][mm] = av.x; As[kb+1][mm] = av.y;
            As[kb+2][mm] = av.z; As[kb+3][mm] = av.w;
        }
        {
            int nn = tid >> 2, kb = (tid & 3) << 2;
            float4 bv = *(const float4*)&wkv[(size_t)(n0 + nn) * 1024 + k0 + kb];
            Bs[kb+0][nn] = bv.x; Bs[kb+1][nn] = bv.y;
            Bs[kb+2][nn] = bv.z; Bs[kb+3][nn] = bv.w;
        }
        __syncthreads();
        #pragma unroll
        for (int kk = 0; kk < 16; kk++) {
            float4 a4 = *(const float4*)&As[kk][ty << 2];
            float4 b4 = *(const float4*)&Bs[kk][tx << 2];
            float a[4] = {a4.x, a4.y, a4.z, a4.w};
            float bb[4] = {b4.x, b4.y, b4.z, b4.w};
            #pragma unroll
            for (int i = 0; i < 4; i++)
                #pragma unroll
                for (int j = 0; j < 4; j++)
                    acc[i][j] += a[i] * bb[j];
        }
        __syncthreads();
    }
    #pragma unroll
    for (int i = 0; i < 4; i++)
        #pragma unroll
        for (int j = 0; j < 4; j++)
            atomicAdd(&g_kv[(size_t)(m0 + (ty<<2) + i) * 1024 + n0 + (tx<<2) + j], acc[i][j]);
}

// ---------------- proj2: kT frags (0-255), vp frags (256-511), ksb (512-515) ----------------
// split-K 16, atomicAdd directly into fragment-ordered fp32 arrays
__global__ void proj2_kernel(const float* __restrict__ wq, const float* __restrict__ wo,
                             const float* __restrict__ bq) {
    int bid = blockIdx.x;
    int tid = threadIdx.x;

    if (bid >= 512) {         // ksb: bq . k
        int warp = tid >> 5, lane = tid & 31;
        int base = (bid - 512) * 32 + warp * 4;
        for (int r = 0; r < 4; r++) {
            int row = base + r;
            const float4* kr = (const float4*)&g_kv[(size_t)row * 1024];
            float s = 0.f;
            #pragma unroll
            for (int i = 0; i < 4; i++) {
                float4 kvv = kr[i*32 + lane];
                float4 bqv = *(const float4*)&bq[(i*32 + lane) << 2];
                s += kvv.x*bqv.x + kvv.y*bqv.y + kvv.z*bqv.z + kvv.w*bqv.w;
            }
            #pragma unroll
            for (int off = 16; off > 0; off >>= 1) s += __shfl_xor_sync(FULLMASK, s, off);
            if (lane == 0) g_ksb[row] = s;
        }
        return;
    }

    __shared__ float As[16][68];
    __shared__ float Bs[16][68];
    bool isK = bid < 256;
    int local = bid & 255;
    int n0 = (local & 7) * 64;
    int m0 = ((local >> 3) & 1) * 64;
    int k0base = (local >> 4) * 32;         // split-K 16
    const float* A = isK ? g_kv : (g_kv + 512);
    const float* B = isK ? wq : wo;
    int tx = tid & 15, ty = tid >> 4;

    float acc[4][4];
    #pragma unroll
    for (int i = 0; i < 4; i++)
        #pragma unroll
        for (int j = 0; j < 4; j++) acc[i][j] = 0.f;

    for (int k0 = k0base; k0 < k0base + 32; k0 += 16) {
        {
            int mm = tid >> 2, kb = (tid & 3) << 2;
            float4 av = *(const float4*)&A[(size_t)(m0 + mm) * 1024 + k0 + kb];
            As[kb+0][mm] = av.x; As[kb+1][mm] = av.y;
            As[kb+2][mm] = av.z; As[kb+3][mm] = av.w;
        }
        if (isK) {            // B = wq: Bs[k][n] = B[k*512 + n]
            int kk = tid >> 4, nb = (tid & 15) << 2;
            float4 bv = *(const float4*)&B[(size_t)(k0 + kk) * 512 + n0 + nb];
            *(float4*)&Bs[kk][nb] = bv;
        } else {              // B = wo^T
            int nn = tid >> 2, kb = (tid & 3) << 2;
            float4 bv = *(const float4*)&B[(size_t)(n0 + nn) * 512 + k0 + kb];
            Bs[kb+0][nn] = bv.x; Bs[kb+1][nn] = bv.y;
            Bs[kb+2][nn] = bv.z; Bs[kb+3][nn] = bv.w;
        }
        __syncthreads();
        #pragma unroll
        for (int kk = 0; kk < 16; kk++) {
            float4 a4 = *(const float4*)&As[kk][ty << 2];
            float4 b4 = *(const float4*)&Bs[kk][tx << 2];
            float a[4] = {a4.x, a4.y, a4.z, a4.w};
            float bb[4] = {b4.x, b4.y, b4.z, b4.w};
            #pragma unroll
            for (int i = 0; i < 4; i++)
                #pragma unroll
                for (int j = 0; j < 4; j++)
                    acc[i][j] += a[i] * bb[j];
        }
        __syncthreads();
    }
    float* kf = (float*)g_kf32;
    float* vf = (float*)g_vf32;
    #pragma unroll
    for (int i = 0; i < 4; i++)
        #pragma unroll
        for (int j = 0; j < 4; j++) {
            int m = m0 + (ty << 2) + i, n = n0 + (tx << 2) + j;
            if (isK) atomicAdd(&kf[kf_idx(m, n)], acc[i][j]);
            else     atomicAdd(&vf[vf_idx(m, n)], acc[i][j]);
        }
}

// ---------------- fused normalize + attention (bf16 mma, fp32 B frags from global) ----------------
// block per (b, t, 32-hw tile); 256 threads (8 warps); ~49KB dyn smem
__global__ void __launch_bounds__(256) attn_kernel(
    const float* __restrict__ x, const float* __restrict__ gamma,
    const float* __restrict__ beta, const float* __restrict__ bo,
    float* __restrict__ out) {
    extern __shared__ uint shu[];
    float* s_scl  = (float*)shu;                     // 512
    float* s_bia  = (float*)(shu + 512);             // 512
    uint*  frag_h = shu + 1024;                      // 8192: [qw(2)][k8(32)][lane(32)][reg(4)]
    float* sh_sf  = (float*)(shu + 1024 + 8192);     // 32 x SSTR fp32 scores
    uint*  sw_u   = shu + 1024 + 8192 + 32*SSTR;     // 32 x WST packed weights
    __shared__ float sksb[64];

    int bi = blockIdx.x;
    int tile = bi & 31, t = 15 - ((bi >> 5) & 15), b = bi >> 9;
    int hw0 = tile * 32;
    int tid = threadIdx.x;
    const int L   = (t + 1) * 4;
    const int L16 = (L + 15) & ~15;

    // ---- per-block norm params + score bias ----
    if (tid < 64) sksb[tid] = g_ksb[b * 64 + tid];
    #pragma unroll
    for (int c = tid; c < 512; c += 256) {
        int g = c >> 4;
        float mu = g_mu  [b * 512 + g * 16 + t];
        float rs = g_rstd[b * 512 + g * 16 + t];
        float sc = rs * gamma[c];
        s_scl[c] = sc;
        s_bia[c] = beta[c] - mu * sc;
    }
    __syncthreads();

    // ---- stage normalized h into fragment-major layout ----
    #pragma unroll
    for (int it = 0; it < 8; it++) {
        int lin = it * 256 + tid;            // 0..2047
        int cpair = lin >> 3;                // 0..255
        int hwq = (lin & 7) << 2;            // 0,4,..,28
        int c0 = cpair * 2;
        const float* xp = x + ((size_t)(b * 512 + c0) * 16 + t) * 1024 + hw0 + hwq;
        float4 x0 = *(const float4*)xp;
        float4 x1 = *(const float4*)(xp + 16384);    // c0+1 row
        float sc0 = s_scl[c0],   bi0 = s_bia[c0];
        float sc1 = s_scl[c0+1], bi1 = s_bia[c0+1];
        int k8 = cpair >> 3;
        int cp7 = cpair & 7;
        int tig_ = cp7 & 3;
        int regc = (cp7 >> 2) << 1;          // 0 or 2
        float xa[4] = {x0.x, x0.y, x0.z, x0.w};
        float xb[4] = {x1.x, x1.y, x1.z, x1.w};
        #pragma unroll
        for (int i = 0; i < 4; i++) {
            int hw = hwq + i;
            int qw = hw >> 4, r = hw & 15;
            int lane2 = (r & 7) * 4 + tig_;
            int reg = regc + (r >> 3);
            frag_h[(qw * 32 + k8) * 128 + lane2 * 4 + reg] =
                packbf(xa[i] * sc0 + bi0, xb[i] * sc1 + bi1);
        }
    }
    __syncthreads();

    int warp = tid >> 5, lane = tid & 31;
    int grp = lane >> 2, tig = lane & 3;

    // ================= scores: warp = one s-tile (8 s), both q-tiles =================
    {
        int st = warp;
        if (st * 8 < L) {
            float4 C0 = {0,0,0,0}, C1 = {0,0,0,0};
            const float4* kf = g_kf32 + ((size_t)(b * 8 + st) * 32) * 32 + lane;
            #pragma unroll 8
            for (int k8 = 0; k8 < 32; k8++) {
                uint4 A0 = *(const uint4*)&frag_h[k8 * 128 + lane * 4];
                uint4 A1 = *(const uint4*)&frag_h[(32 + k8) * 128 + lane * 4];
                float4 f = kf[k8 * 32];
                uint bv0 = packbf(f.x, f.y);
                uint bv1 = packbf(f.z, f.w);
                mma_bf16(C0, A0.x, A0.y, A0.z, A0.w, bv0, bv1);
                mma_bf16(C1, A1.x, A1.y, A1.z, A1.w, bv0, bv1);
            }
            int s = st * 8 + 2 * tig;
            if (s < L) {
                float kb = sksb[s];
                sh_sf[ grp      * SSTR + s] = (C0.x + kb) * SCALE;
                sh_sf[(grp + 8) * SSTR + s] = (C0.z + kb) * SCALE;
                sh_sf[(16 + grp) * SSTR + s] = (C1.x + kb) * SCALE;
                sh_sf[(24 + grp) * SSTR + s] = (C1.z + kb) * SCALE;
            }
            if (s + 1 < L) {
                float kb = sksb[s + 1];
                sh_sf[ grp      * SSTR + s + 1] = (C0.y + kb) * SCALE;
                sh_sf[(grp + 8) * SSTR + s + 1] = (C0.w + kb) * SCALE;
                sh_sf[(16 + grp) * SSTR + s + 1] = (C1.y + kb) * SCALE;
                sh_sf[(24 + grp) * SSTR + s + 1] = (C1.w + kb) * SCALE;
            }
        }
    }
    __syncthreads();

    // ================= softmax (warp = 4 rows) -> packed bf16x2 weights =================
    for (int r = 0; r < 4; r++) {
        int q = warp * 4 + r;
        float v0 = (lane      < L) ? sh_sf[q * SSTR + lane     ] : -INFINITY;
        float v1 = (lane + 32 < L) ? sh_sf[q * SSTR + lane + 32] : -INFINITY;
        float mx = fmaxf(v0, v1);
        #pragma unroll
        for (int off = 16; off > 0; off >>= 1) mx = fmaxf(mx, __shfl_xor_sync(FULLMASK, mx, off));
        float e0 = __expf(v0 - mx), e1 = __expf(v1 - mx);
        float ds = e0 + e1;
        #pragma unroll
        for (int off = 16; off > 0; off >>= 1) ds += __shfl_xor_sync(FULLMASK, ds, off);
        float inv = 1.f / ds;
        float we = e0 * inv, wo_ = e1 * inv;     // s=lane, s=lane+32 (0 beyond L)
        int i0 = (2 * lane) & 31, i1 = (2 * lane + 1) & 31;
        float alo = __shfl_sync(FULLMASK, we,  i0), blo = __shfl_sync(FULLMASK, we,  i1);
        float ahi = __shfl_sync(FULLMASK, wo_, i0), bhi = __shfl_sync(FULLMASK, wo_, i1);
        float wa = lane < 16 ? alo : ahi;
        float wb = lane < 16 ? blo : bhi;
        sw_u[q * WST + lane] = packbf(wa, wb);
    }
    __syncthreads();

    // ================= combine: warp owns 64 c cols, both q-tiles; fused epilogue =================
    {
        const int kmax = L16 >> 4;
        int w = warp;
        #pragma unroll
        for (int ch2 = 0; ch2 < 2; ch2++) {
            float4 D0[4], D1[4];
            #pragma unroll
            for (int nt = 0; nt < 4; nt++) {
                D0[nt] = make_float4(0.f, 0.f, 0.f, 0.f);
                D1[nt] = make_float4(0.f, 0.f, 0.f, 0.f);
            }
            for (int k8s = 0; k8s < kmax; k8s++) {
                int sp = k8s * 8;
                uint a00 = sw_u[ grp       * WST + sp + tig];
                uint a01 = sw_u[(grp + 8)  * WST + sp + tig];
                uint a02 = sw_u[ grp       * WST + sp + tig + 4];
                uint a03 = sw_u[(grp + 8)  * WST + sp + tig + 4];
                uint a10 = sw_u[(16 + grp) * WST + sp + tig];
                uint a11 = sw_u[(24 + grp) * WST + sp + tig];
                uint a12 = sw_u[(16 + grp) * WST + sp + tig + 4];
                uint a13 = sw_u[(24 + grp) * WST + sp + tig + 4];
                #pragma unroll
                for (int nt = 0; nt < 4; nt++) {
                    int ct = w * 8 + ch2 * 4 + nt;
                    float4 fv = g_vf32[((size_t)(b * 4 + k8s) * 64 + ct) * 32 + lane];
                    uint bv0 = packbf(fv.x, fv.y);
                    uint bv1 = packbf(fv.z, fv.w);
                    mma_bf16(D0[nt], a00, a01, a02, a03, bv0, bv1);
                    mma_bf16(D1[nt], a10, a11, a12, a13, bv0, bv1);
                }
            }
            // fused epilogue: out = x + o + bo
            #pragma unroll
            for (int nt = 0; nt < 4; nt++) {
                int ct = w * 8 + ch2 * 4 + nt;
                int c0 = ct * 8 + 2 * tig;
                float bo0 = bo[c0], bo1 = bo[c0 + 1];
                size_t gA0 = ((size_t)(b * 512 + c0) * 16 + t) * 1024 + hw0 + grp;
                size_t gA1 = gA0 + 16384;     // c0+1 row
                out[gA0]      = x[gA0]      + D0[nt].x + bo0;
                out[gA1]      = x[gA1]      + D0[nt].y + bo1;
                out[gA0 + 8]  = x[gA0 + 8]  + D0[nt].z + bo0;
                out[gA1 + 8]  = x[gA1 + 8]  + D0[nt].w + bo1;
                size_t gB0 = gA0 + 16;        // q-tile 1: hw +16
                size_t gB1 = gA1 + 16;
                out[gB0]      = x[gB0]      + D1[nt].x + bo0;
                out[gB1]      = x[gB1]      + D1[nt].y + bo1;
                out[gB0 + 8]  = x[gB0 + 8]  + D1[nt].z + bo0;
                out[gB1 + 8]  = x[gB1 + 8]  + D1[nt].w + bo1;
            }
        }
    }
}

// ---------------- launch ----------------
extern "C" void kernel_launch(void* const* d_in, const int* in_sizes, int n_in,
                              void* d_out, int out_size) {
    const float* x       = (const float*)d_in[0];
    const float* context = (const float*)d_in[1];
    const float* gamma   = (const float*)d_in[2];
    const float* beta    = (const float*)d_in[3];
    const float* wq      = (const float*)d_in[4];
    const float* bq      = (const float*)d_in[5];
    const float* wkv     = (const float*)d_in[6];
    const float* bkv     = (const float*)d_in[7];
    const float* wo      = (const float*)d_in[8];
    const float* bo      = (const float*)d_in[9];
    float* out = (float*)d_out;

    const int SMEM_BYTES = (1024 + 8192 + 32*SSTR + 32*WST) * 4;   // 50176
    cudaFuncSetAttribute(attn_kernel, cudaFuncAttributeMaxDynamicSharedMemorySize, SMEM_BYTES);

    seed_kernel<<<256, 256>>>(bkv);
    pre1_kernel<<<1280, 256>>>(x, context, wkv);
    proj2_kernel<<<516, 256>>>(wq, wo, bq);
    attn_kernel<<<Bz * Tt * 32, 256, SMEM_BYTES>>>(x, gamma, beta, bo, out);
}

// round 14
// speedup vs baseline: 1.0032x; 1.0032x over previous
#include <cuda_runtime.h>
#include <cuda_bf16.h>
#include <math.h>

#define Bz   2
#define Cc   512
#define Tt   16
#define HWp  1024
#define EPS  1e-5f
#define SCALE 0.04419417382415922f  // 512^-0.5
#define FULLMASK 0xffffffffu
#define SSTR 68     // fp32 score row stride
#define WST  36     // packed weight row stride (uints)

typedef unsigned int uint;

// ---------------- helpers ----------------
__device__ __forceinline__ uint packbf(float lo, float hi) {
    uint r; asm("cvt.rn.bf16x2.f32 %0, %1, %2;" : "=r"(r) : "f"(hi), "f"(lo)); return r;
}
__device__ __forceinline__ void mma_bf16(float4& d, uint a0, uint a1, uint a2, uint a3,
                                         uint b0, uint b1) {
    asm volatile("mma.sync.aligned.m16n8k16.row.col.f32.bf16.bf16.f32 "
                 "{%0,%1,%2,%3}, {%4,%5,%6,%7}, {%8,%9}, {%0,%1,%2,%3};"
                 : "+f"(d.x), "+f"(d.y), "+f"(d.z), "+f"(d.w)
                 : "r"(a0), "r"(a1), "r"(a2), "r"(a3), "r"(b0), "r"(b1));
}

// ---------------- scratch ----------------
__device__ float  g_mu  [Bz * 32 * Tt];
__device__ float  g_rstd[Bz * 32 * Tt];
__device__ float  g_kv  [128 * 1024];     // [b*64+s][2C]
__device__ float  g_kpT [512 * 128];      // fp32 [c][b*64+s]
__device__ float  g_vp  [128 * 512];      // fp32 [b*64+s][c]
__device__ float4 g_kf32[16384];          // score B frags fp32: [b][st(8)][k8(32)][lane(32)]
__device__ float4 g_vf32[16384];          // combine B frags fp32: [b][k8s(4)][ct(64)][lane(32)]
__device__ float  g_ksb [128];

// ---------------- seed: g_kv = bkv bcast, g_kpT = 0, g_vp = 0 ----------------
__global__ void seed_kernel(const float* __restrict__ bkv) {
    int i4 = (blockIdx.x * 256 + threadIdx.x) * 4;   // 0..262140
    if (i4 < 131072) {
        float4 bv = *(const float4*)&bkv[i4 & 1023];
        *(float4*)&g_kv[i4] = bv;
    } else if (i4 < 196608) {
        *(float4*)&g_kpT[i4 - 131072] = make_float4(0.f, 0.f, 0.f, 0.f);
    } else {
        *(float4*)&g_vp[i4 - 196608] = make_float4(0.f, 0.f, 0.f, 0.f);
    }
}

// ---------------- pre1: kv gemm (blocks 0-255) + gn stats (blocks 256-1279) ----------------
__global__ void pre1_kernel(const float* __restrict__ x, const float* __restrict__ context,
                            const float* __restrict__ wkv) {
    int bid = blockIdx.x;
    int tid = threadIdx.x;

    if (bid >= 256) {     // ---- groupnorm stats ----
        int idx = bid - 256;                 // b*512 + g*16 + t
        int b = idx >> 9, g = (idx >> 4) & 31, t = idx & 15;
        float s = 0.f, sq = 0.f;
        for (int ci = 0; ci < 16; ci++) {
            const float4* row = (const float4*)(x + (size_t)(((b*Cc + g*16 + ci)*Tt + t)) * HWp);
            float4 v = row[tid];
            s  += v.x + v.y + v.z + v.w;
            sq += v.x*v.x + v.y*v.y + v.z*v.z + v.w*v.w;
        }
        __shared__ float s1[256], s2[256];
        s1[tid] = s; s2[tid] = sq;
        __syncthreads();
        for (int st = 128; st > 0; st >>= 1) {
            if (tid < st) { s1[tid] += s1[tid + st]; s2[tid] += s2[tid + st]; }
            __syncthreads();
        }
        if (tid == 0) {
            const float invN = 1.f / 16384.f;
            float mu  = s1[0] * invN;
            float var = s2[0] * invN - mu * mu;
            g_mu[idx] = mu;
            g_rstd[idx] = rsqrtf(var + EPS);
        }
        return;
    }

    // ---- kv = context @ wkv^T (split-K 8, atomic into seeded g_kv) ----
    __shared__ float As[16][68];
    __shared__ float Bs[16][68];
    int n0 = (bid & 15) * 64;
    int m0 = ((bid >> 4) & 1) * 64;
    int k0base = (bid >> 5) * 128;
    int tx = tid & 15, ty = tid >> 4;

    float acc[4][4];
    #pragma unroll
    for (int i = 0; i < 4; i++)
        #pragma unroll
        for (int j = 0; j < 4; j++) acc[i][j] = 0.f;

    for (int k0 = k0base; k0 < k0base + 128; k0 += 16) {
        {
            int mm = tid >> 2, kb = (tid & 3) << 2;
            float4 av = *(const float4*)&context[(size_t)(m0 + mm) * 1024 + k0 + kb];
            As[kb+0][mm] = av.x; As[kb+1][mm] = av.y;
            As[kb+2][mm] = av.z; As[kb+3][mm] = av.w;
        }
        {
            int nn = tid >> 2, kb = (tid & 3) << 2;
            float4 bv = *(const float4*)&wkv[(size_t)(n0 + nn) * 1024 + k0 + kb];
            Bs[kb+0][nn] = bv.x; Bs[kb+1][nn] = bv.y;
            Bs[kb+2][nn] = bv.z; Bs[kb+3][nn] = bv.w;
        }
        __syncthreads();
        #pragma unroll
        for (int kk = 0; kk < 16; kk++) {
            float4 a4 = *(const float4*)&As[kk][ty << 2];
            float4 b4 = *(const float4*)&Bs[kk][tx << 2];
            float a[4] = {a4.x, a4.y, a4.z, a4.w};
            float bb[4] = {b4.x, b4.y, b4.z, b4.w};
            #pragma unroll
            for (int i = 0; i < 4; i++)
                #pragma unroll
                for (int j = 0; j < 4; j++)
                    acc[i][j] += a[i] * bb[j];
        }
        __syncthreads();
    }
    #pragma unroll
    for (int i = 0; i < 4; i++)
        #pragma unroll
        for (int j = 0; j < 4; j++)
            atomicAdd(&g_kv[(size_t)(m0 + (ty<<2) + i) * 1024 + n0 + (tx<<2) + j], acc[i][j]);
}

// ---------------- proj2: kT (0-127), vp (128-255), ksb (256-259); split-K 8 ----------------
__global__ void proj2_kernel(const float* __restrict__ wq, const float* __restrict__ wo,
                             const float* __restrict__ bq) {
    int bid = blockIdx.x;
    int tid = threadIdx.x;

    if (bid >= 256) {         // ksb: bq . k
        int warp = tid >> 5, lane = tid & 31;
        int base = (bid - 256) * 32 + warp * 4;
        for (int r = 0; r < 4; r++) {
            int row = base + r;
            const float4* kr = (const float4*)&g_kv[(size_t)row * 1024];
            float s = 0.f;
            #pragma unroll
            for (int i = 0; i < 4; i++) {
                float4 kvv = kr[i*32 + lane];
                float4 bqv = *(const float4*)&bq[(i*32 + lane) << 2];
                s += kvv.x*bqv.x + kvv.y*bqv.y + kvv.z*bqv.z + kvv.w*bqv.w;
            }
            #pragma unroll
            for (int off = 16; off > 0; off >>= 1) s += __shfl_xor_sync(FULLMASK, s, off);
            if (lane == 0) g_ksb[row] = s;
        }
        return;
    }

    __shared__ float As[16][68];
    __shared__ float Bs[16][68];
    bool isK = bid < 128;
    int local = bid & 127;
    int n0 = (local & 7) * 64;
    int m0 = ((local >> 3) & 1) * 64;
    int k0base = (local >> 4) * 64;         // split-K 8
    const float* A = isK ? g_kv : (g_kv + 512);
    const float* B = isK ? wq : wo;
    int tx = tid & 15, ty = tid >> 4;

    float acc[4][4];
    #pragma unroll
    for (int i = 0; i < 4; i++)
        #pragma unroll
        for (int j = 0; j < 4; j++) acc[i][j] = 0.f;

    for (int k0 = k0base; k0 < k0base + 64; k0 += 16) {
        {
            int mm = tid >> 2, kb = (tid & 3) << 2;
            float4 av = *(const float4*)&A[(size_t)(m0 + mm) * 1024 + k0 + kb];
            As[kb+0][mm] = av.x; As[kb+1][mm] = av.y;
            As[kb+2][mm] = av.z; As[kb+3][mm] = av.w;
        }
        if (isK) {            // B = wq: Bs[k][n] = B[k*512 + n]
            int kk = tid >> 4, nb = (tid & 15) << 2;
            float4 bv = *(const float4*)&B[(size_t)(k0 + kk) * 512 + n0 + nb];
            *(float4*)&Bs[kk][nb] = bv;
        } else {              // B = wo^T
            int nn = tid >> 2, kb = (tid & 3) << 2;
            float4 bv = *(const float4*)&B[(size_t)(n0 + nn) * 512 + k0 + kb];
            Bs[kb+0][nn] = bv.x; Bs[kb+1][nn] = bv.y;
            Bs[kb+2][nn] = bv.z; Bs[kb+3][nn] = bv.w;
        }
        __syncthreads();
        #pragma unroll
        for (int kk = 0; kk < 16; kk++) {
            float4 a4 = *(const float4*)&As[kk][ty << 2];
            float4 b4 = *(const float4*)&Bs[kk][tx << 2];
            float a[4] = {a4.x, a4.y, a4.z, a4.w};
            float bb[4] = {b4.x, b4.y, b4.z, b4.w};
            #pragma unroll
            for (int i = 0; i < 4; i++)
                #pragma unroll
                for (int j = 0; j < 4; j++)
                    acc[i][j] += a[i] * bb[j];
        }
        __syncthreads();
    }
    #pragma unroll
    for (int i = 0; i < 4; i++)
        #pragma unroll
        for (int j = 0; j < 4; j++) {
            int m = m0 + (ty << 2) + i, n = n0 + (tx << 2) + j;
            if (isK) atomicAdd(&g_kpT[(size_t)n * 128 + m], acc[i][j]);
            else     atomicAdd(&g_vp [(size_t)m * 512 + n], acc[i][j]);
        }
}

// ---------------- cvt: dense fp32 k'/v' -> fragment-ordered fp32 float4 ----------------
// mapping identical to Round-13's verified kf_idx/vf_idx (inverted)
__global__ void cvt_kernel() {
    int j = blockIdx.x * 256 + threadIdx.x;   // 0..32767
    if (j < 16384) {          // score B frags: [b][st][k8][lane]
        int lane = j & 31;
        int k8   = (j >> 5) & 31;
        int st   = (j >> 10) & 7;
        int b    = (j >> 13) & 1;
        int tig = lane & 3, grp = lane >> 2;
        int scol = b * 64 + st * 8 + grp;
        int c00 = k8 * 16 + tig * 2;
        int c10 = c00 + 8;
        float4 f;
        f.x = g_kpT[(size_t)c00 * 128 + scol];
        f.y = g_kpT[(size_t)(c00+1) * 128 + scol];
        f.z = g_kpT[(size_t)c10 * 128 + scol];
        f.w = g_kpT[(size_t)(c10+1) * 128 + scol];
        g_kf32[j] = f;
    } else {                  // combine B frags: [b][k8s][ct][lane]
        int j2 = j - 16384;
        int lane = j2 & 31;
        int ct   = (j2 >> 5) & 63;
        int k8s  = (j2 >> 11) & 3;
        int b    = (j2 >> 13) & 1;
        int tig = lane & 3, grp = lane >> 2;
        int c = ct * 8 + grp;
        int srow = b * 64 + k8s * 16 + tig * 2;
        float4 f;
        f.x = g_vp[(size_t)srow     * 512 + c];
        f.y = g_vp[(size_t)(srow+1) * 512 + c];
        f.z = g_vp[(size_t)(srow+8) * 512 + c];
        f.w = g_vp[(size_t)(srow+9) * 512 + c];
        g_vf32[j2] = f;
    }
}

// ---------------- fused normalize + attention (bf16 mma, fp32 B frags from global) ----------------
// block per (b, t, 32-hw tile); 256 threads (8 warps); ~49KB dyn smem
__global__ void __launch_bounds__(256) attn_kernel(
    const float* __restrict__ x, const float* __restrict__ gamma,
    const float* __restrict__ beta, const float* __restrict__ bo,
    float* __restrict__ out) {
    extern __shared__ uint shu[];
    float* s_scl  = (float*)shu;                     // 512
    float* s_bia  = (float*)(shu + 512);             // 512
    uint*  frag_h = shu + 1024;                      // 8192: [qw(2)][k8(32)][lane(32)][reg(4)]
    float* sh_sf  = (float*)(shu + 1024 + 8192);     // 32 x SSTR fp32 scores
    uint*  sw_u   = shu + 1024 + 8192 + 32*SSTR;     // 32 x WST packed weights
    __shared__ float sksb[64];

    int bi = blockIdx.x;
    int tile = bi & 31, t = 15 - ((bi >> 5) & 15), b = bi >> 9;
    int hw0 = tile * 32;
    int tid = threadIdx.x;
    const int L   = (t + 1) * 4;
    const int L16 = (L + 15) & ~15;

    // ---- per-block norm params + score bias ----
    if (tid < 64) sksb[tid] = g_ksb[b * 64 + tid];
    #pragma unroll
    for (int c = tid; c < 512; c += 256) {
        int g = c >> 4;
        float mu = g_mu  [b * 512 + g * 16 + t];
        float rs = g_rstd[b * 512 + g * 16 + t];
        float sc = rs * gamma[c];
        s_scl[c] = sc;
        s_bia[c] = beta[c] - mu * sc;
    }
    __syncthreads();

    // ---- stage normalized h into fragment-major layout ----
    #pragma unroll
    for (int it = 0; it < 8; it++) {
        int lin = it * 256 + tid;            // 0..2047
        int cpair = lin >> 3;                // 0..255
        int hwq = (lin & 7) << 2;            // 0,4,..,28
        int c0 = cpair * 2;
        const float* xp = x + ((size_t)(b * 512 + c0) * 16 + t) * 1024 + hw0 + hwq;
        float4 x0 = *(const float4*)xp;
        float4 x1 = *(const float4*)(xp + 16384);    // c0+1 row
        float sc0 = s_scl[c0],   bi0 = s_bia[c0];
        float sc1 = s_scl[c0+1], bi1 = s_bia[c0+1];
        int k8 = cpair >> 3;
        int cp7 = cpair & 7;
        int tig_ = cp7 & 3;
        int regc = (cp7 >> 2) << 1;          // 0 or 2
        float xa[4] = {x0.x, x0.y, x0.z, x0.w};
        float xb[4] = {x1.x, x1.y, x1.z, x1.w};
        #pragma unroll
        for (int i = 0; i < 4; i++) {
            int hw = hwq + i;
            int qw = hw >> 4, r = hw & 15;
            int lane2 = (r & 7) * 4 + tig_;
            int reg = regc + (r >> 3);
            frag_h[(qw * 32 + k8) * 128 + lane2 * 4 + reg] =
                packbf(xa[i] * sc0 + bi0, xb[i] * sc1 + bi1);
        }
    }
    __syncthreads();

    int warp = tid >> 5, lane = tid & 31;
    int grp = lane >> 2, tig = lane & 3;

    // ================= scores: warp = one s-tile (8 s), both q-tiles =================
    {
        int st = warp;
        if (st * 8 < L) {
            float4 C0 = {0,0,0,0}, C1 = {0,0,0,0};
            const float4* kf = g_kf32 + ((size_t)(b * 8 + st) * 32) * 32 + lane;
            #pragma unroll 8
            for (int k8 = 0; k8 < 32; k8++) {
                uint4 A0 = *(const uint4*)&frag_h[k8 * 128 + lane * 4];
                uint4 A1 = *(const uint4*)&frag_h[(32 + k8) * 128 + lane * 4];
                float4 f = kf[k8 * 32];
                uint bv0 = packbf(f.x, f.y);
                uint bv1 = packbf(f.z, f.w);
                mma_bf16(C0, A0.x, A0.y, A0.z, A0.w, bv0, bv1);
                mma_bf16(C1, A1.x, A1.y, A1.z, A1.w, bv0, bv1);
            }
            int s = st * 8 + 2 * tig;
            if (s < L) {
                float kb = sksb[s];
                sh_sf[ grp      * SSTR + s] = (C0.x + kb) * SCALE;
                sh_sf[(grp + 8) * SSTR + s] = (C0.z + kb) * SCALE;
                sh_sf[(16 + grp) * SSTR + s] = (C1.x + kb) * SCALE;
                sh_sf[(24 + grp) * SSTR + s] = (C1.z + kb) * SCALE;
            }
            if (s + 1 < L) {
                float kb = sksb[s + 1];
                sh_sf[ grp      * SSTR + s + 1] = (C0.y + kb) * SCALE;
                sh_sf[(grp + 8) * SSTR + s + 1] = (C0.w + kb) * SCALE;
                sh_sf[(16 + grp) * SSTR + s + 1] = (C1.y + kb) * SCALE;
                sh_sf[(24 + grp) * SSTR + s + 1] = (C1.w + kb) * SCALE;
            }
        }
    }
    __syncthreads();

    // ================= softmax (warp = 4 rows) -> packed bf16x2 weights =================
    for (int r = 0; r < 4; r++) {
        int q = warp * 4 + r;
        float v0 = (lane      < L) ? sh_sf[q * SSTR + lane     ] : -INFINITY;
        float v1 = (lane + 32 < L) ? sh_sf[q * SSTR + lane + 32] : -INFINITY;
        float mx = fmaxf(v0, v1);
        #pragma unroll
        for (int off = 16; off > 0; off >>= 1) mx = fmaxf(mx, __shfl_xor_sync(FULLMASK, mx, off));
        float e0 = __expf(v0 - mx), e1 = __expf(v1 - mx);
        float ds = e0 + e1;
        #pragma unroll
        for (int off = 16; off > 0; off >>= 1) ds += __shfl_xor_sync(FULLMASK, ds, off);
        float inv = 1.f / ds;
        float we = e0 * inv, wo_ = e1 * inv;     // s=lane, s=lane+32 (0 beyond L)
        int i0 = (2 * lane) & 31, i1 = (2 * lane + 1) & 31;
        float alo = __shfl_sync(FULLMASK, we,  i0), blo = __shfl_sync(FULLMASK, we,  i1);
        float ahi = __shfl_sync(FULLMASK, wo_, i0), bhi = __shfl_sync(FULLMASK, wo_, i1);
        float wa = lane < 16 ? alo : ahi;
        float wb = lane < 16 ? blo : bhi;
        sw_u[q * WST + lane] = packbf(wa, wb);
    }
    __syncthreads();

    // ================= combine: warp owns 64 c cols, both q-tiles; fused epilogue =================
    {
        const int kmax = L16 >> 4;
        int w = warp;
        #pragma unroll
        for (int ch2 = 0; ch2 < 2; ch2++) {
            float4 D0[4], D1[4];
            #pragma unroll
            for (int nt = 0; nt < 4; nt++) {
                D0[nt] = make_float4(0.f, 0.f, 0.f, 0.f);
                D1[nt] = make_float4(0.f, 0.f, 0.f, 0.f);
            }
            for (int k8s = 0; k8s < kmax; k8s++) {
                int sp = k8s * 8;
                uint a00 = sw_u[ grp       * WST + sp + tig];
                uint a01 = sw_u[(grp + 8)  * WST + sp + tig];
                uint a02 = sw_u[ grp       * WST + sp + tig + 4];
                uint a03 = sw_u[(grp + 8)  * WST + sp + tig + 4];
                uint a10 = sw_u[(16 + grp) * WST + sp + tig];
                uint a11 = sw_u[(24 + grp) * WST + sp + tig];
                uint a12 = sw_u[(16 + grp) * WST + sp + tig + 4];
                uint a13 = sw_u[(24 + grp) * WST + sp + tig + 4];
                #pragma unroll
                for (int nt = 0; nt < 4; nt++) {
                    int ct = w * 8 + ch2 * 4 + nt;
                    float4 fv = g_vf32[((size_t)(b * 4 + k8s) * 64 + ct) * 32 + lane];
                    uint bv0 = packbf(fv.x, fv.y);
                    uint bv1 = packbf(fv.z, fv.w);
                    mma_bf16(D0[nt], a00, a01, a02, a03, bv0, bv1);
                    mma_bf16(D1[nt], a10, a11, a12, a13, bv0, bv1);
                }
            }
            // fused epilogue: out = x + o + bo
            #pragma unroll
            for (int nt = 0; nt < 4; nt++) {
                int ct = w * 8 + ch2 * 4 + nt;
                int c0 = ct * 8 + 2 * tig;
                float bo0 = bo[c0], bo1 = bo[c0 + 1];
                size_t gA0 = ((size_t)(b * 512 + c0) * 16 + t) * 1024 + hw0 + grp;
                size_t gA1 = gA0 + 16384;     // c0+1 row
                out[gA0]      = x[gA0]      + D0[nt].x + bo0;
                out[gA1]      = x[gA1]      + D0[nt].y + bo1;
                out[gA0 + 8]  = x[gA0 + 8]  + D0[nt].z + bo0;
                out[gA1 + 8]  = x[gA1 + 8]  + D0[nt].w + bo1;
                size_t gB0 = gA0 + 16;        // q-tile 1: hw +16
                size_t gB1 = gA1 + 16;
                out[gB0]      = x[gB0]      + D1[nt].x + bo0;
                out[gB1]      = x[gB1]      + D1[nt].y + bo1;
                out[gB0 + 8]  = x[gB0 + 8]  + D1[nt].z + bo0;
                out[gB1 + 8]  = x[gB1 + 8]  + D1[nt].w + bo1;
            }
        }
    }
}

// ---------------- launch ----------------
extern "C" void kernel_launch(void* const* d_in, const int* in_sizes, int n_in,
                              void* d_out, int out_size) {
    const float* x       = (const float*)d_in[0];
    const float* context = (const float*)d_in[1];
    const float* gamma   = (const float*)d_in[2];
    const float* beta    = (const float*)d_in[3];
    const float* wq      = (const float*)d_in[4];
    const float* bq      = (const float*)d_in[5];
    const float* wkv     = (const float*)d_in[6];
    const float* bkv     = (const float*)d_in[7];
    const float* wo      = (const float*)d_in[8];
    const float* bo      = (const float*)d_in[9];
    float* out = (float*)d_out;

    const int SMEM_BYTES = (1024 + 8192 + 32*SSTR + 32*WST) * 4;   // 50176
    cudaFuncSetAttribute(attn_kernel, cudaFuncAttributeMaxDynamicSharedMemorySize, SMEM_BYTES);

    seed_kernel<<<256, 256>>>(bkv);
    pre1_kernel<<<1280, 256>>>(x, context, wkv);
    proj2_kernel<<<260, 256>>>(wq, wo, bq);
    cvt_kernel<<<128, 256>>>();
    attn_kernel<<<Bz * Tt * 32, 256, SMEM_BYTES>>>(x, gamma, beta, bo, out);
}

// round 15
// speedup vs baseline: 1.1000x; 1.0964x over previous
#include <cuda_runtime.h>
#include <cuda_bf16.h>
#include <math.h>

#define Bz   2
#define Cc   512
#define Tt   16
#define HWp  1024
#define EPS  1e-5f
#define SCALE 0.04419417382415922f  // 512^-0.5
#define FULLMASK 0xffffffffu
#define SSTR 68     // fp32 score row stride
#define WST  36     // packed weight row stride (uints)

typedef unsigned int uint;

// ---------------- helpers ----------------
__device__ __forceinline__ uint packbf(float lo, float hi) {
    uint r; asm("cvt.rn.bf16x2.f32 %0, %1, %2;" : "=r"(r) : "f"(hi), "f"(lo)); return r;
}
__device__ __forceinline__ void mma_bf16(float4& d, uint a0, uint a1, uint a2, uint a3,
                                         uint b0, uint b1) {
    asm volatile("mma.sync.aligned.m16n8k16.row.col.f32.bf16.bf16.f32 "
                 "{%0,%1,%2,%3}, {%4,%5,%6,%7}, {%8,%9}, {%0,%1,%2,%3};"
                 : "+f"(d.x), "+f"(d.y), "+f"(d.z), "+f"(d.w)
                 : "r"(a0), "r"(a1), "r"(a2), "r"(a3), "r"(b0), "r"(b1));
}

// ---------------- scratch ----------------
__device__ float  g_mu  [Bz * 32 * Tt];
__device__ float  g_rstd[Bz * 32 * Tt];
__device__ float  g_kv  [128 * 1024];     // [b*64+s][2C]
__device__ float  g_kpT [512 * 128];      // fp32 [c][b*64+s]
__device__ float  g_vp  [128 * 512];      // fp32 [b*64+s][c]
__device__ uint2  g_kf  [16384];          // score B frags bf16x2: [b][st(8)][k8(32)][lane(32)]
__device__ uint2  g_vf  [16384];          // combine B frags bf16x2: [b][k8s(4)][ct(64)][lane(32)]
__device__ float  g_ksb [128];

// ---------------- seed: g_kv = bkv bcast, g_kpT = 0, g_vp = 0 ----------------
__global__ void seed_kernel(const float* __restrict__ bkv) {
    int i4 = (blockIdx.x * 256 + threadIdx.x) * 4;   // 0..262140
    if (i4 < 131072) {
        float4 bv = *(const float4*)&bkv[i4 & 1023];
        *(float4*)&g_kv[i4] = bv;
    } else if (i4 < 196608) {
        *(float4*)&g_kpT[i4 - 131072] = make_float4(0.f, 0.f, 0.f, 0.f);
    } else {
        *(float4*)&g_vp[i4 - 196608] = make_float4(0.f, 0.f, 0.f, 0.f);
    }
}

// ---------------- kv = context @ wkv^T (split-K 8, atomic) ----------------
__global__ void kv_kernel(const float* __restrict__ context, const float* __restrict__ wkv) {
    int bid = blockIdx.x;
    int tid = threadIdx.x;
    __shared__ float As[16][68];
    __shared__ float Bs[16][68];
    int n0 = (bid & 15) * 64;
    int m0 = ((bid >> 4) & 1) * 64;
    int k0base = (bid >> 5) * 128;
    int tx = tid & 15, ty = tid >> 4;

    float acc[4][4];
    #pragma unroll
    for (int i = 0; i < 4; i++)
        #pragma unroll
        for (int j = 0; j < 4; j++) acc[i][j] = 0.f;

    for (int k0 = k0base; k0 < k0base + 128; k0 += 16) {
        {
            int mm = tid >> 2, kb = (tid & 3) << 2;
            float4 av = *(const float4*)&context[(size_t)(m0 + mm) * 1024 + k0 + kb];
            As[kb+0][mm] = av.x; As[kb+1][mm] = av.y;
            As[kb+2][mm] = av.z; As[kb+3][mm] = av.w;
        }
        {
            int nn = tid >> 2, kb = (tid & 3) << 2;
            float4 bv = *(const float4*)&wkv[(size_t)(n0 + nn) * 1024 + k0 + kb];
            Bs[kb+0][nn] = bv.x; Bs[kb+1][nn] = bv.y;
            Bs[kb+2][nn] = bv.z; Bs[kb+3][nn] = bv.w;
        }
        __syncthreads();
        #pragma unroll
        for (int kk = 0; kk < 16; kk++) {
            float4 a4 = *(const float4*)&As[kk][ty << 2];
            float4 b4 = *(const float4*)&Bs[kk][tx << 2];
            float a[4] = {a4.x, a4.y, a4.z, a4.w};
            float bb[4] = {b4.x, b4.y, b4.z, b4.w};
            #pragma unroll
            for (int i = 0; i < 4; i++)
                #pragma unroll
                for (int j = 0; j < 4; j++)
                    acc[i][j] += a[i] * bb[j];
        }
        __syncthreads();
    }
    #pragma unroll
    for (int i = 0; i < 4; i++)
        #pragma unroll
        for (int j = 0; j < 4; j++)
            atomicAdd(&g_kv[(size_t)(m0 + (ty<<2) + i) * 1024 + n0 + (tx<<2) + j], acc[i][j]);
}

// ---------------- mid: kT (0-127), vp (128-255), ksb (256-259), gn stats (260-1283) ----------------
__global__ void mid_kernel(const float* __restrict__ x, const float* __restrict__ wq,
                           const float* __restrict__ wo, const float* __restrict__ bq) {
    int bid = blockIdx.x;
    int tid = threadIdx.x;

    if (bid >= 260) {     // ---- groupnorm stats (independent of kv) ----
        int idx = bid - 260;                 // b*512 + g*16 + t
        int b = idx >> 9, g = (idx >> 4) & 31, t = idx & 15;
        float s = 0.f, sq = 0.f;
        for (int ci = 0; ci < 16; ci++) {
            const float4* row = (const float4*)(x + (size_t)(((b*Cc + g*16 + ci)*Tt + t)) * HWp);
            float4 v = row[tid];
            s  += v.x + v.y + v.z + v.w;
            sq += v.x*v.x + v.y*v.y + v.z*v.z + v.w*v.w;
        }
        __shared__ float s1[256], s2[256];
        s1[tid] = s; s2[tid] = sq;
        __syncthreads();
        for (int st = 128; st > 0; st >>= 1) {
            if (tid < st) { s1[tid] += s1[tid + st]; s2[tid] += s2[tid + st]; }
            __syncthreads();
        }
        if (tid == 0) {
            const float invN = 1.f / 16384.f;
            float mu  = s1[0] * invN;
            float var = s2[0] * invN - mu * mu;
            g_mu[idx] = mu;
            g_rstd[idx] = rsqrtf(var + EPS);
        }
        return;
    }

    if (bid >= 256) {         // ksb: bq . k
        int warp = tid >> 5, lane = tid & 31;
        int base = (bid - 256) * 32 + warp * 4;
        for (int r = 0; r < 4; r++) {
            int row = base + r;
            const float4* kr = (const float4*)&g_kv[(size_t)row * 1024];
            float s = 0.f;
            #pragma unroll
            for (int i = 0; i < 4; i++) {
                float4 kvv = kr[i*32 + lane];
                float4 bqv = *(const float4*)&bq[(i*32 + lane) << 2];
                s += kvv.x*bqv.x + kvv.y*bqv.y + kvv.z*bqv.z + kvv.w*bqv.w;
            }
            #pragma unroll
            for (int off = 16; off > 0; off >>= 1) s += __shfl_xor_sync(FULLMASK, s, off);
            if (lane == 0) g_ksb[row] = s;
        }
        return;
    }

    __shared__ float As[16][68];
    __shared__ float Bs[16][68];
    bool isK = bid < 128;
    int local = bid & 127;
    int n0 = (local & 7) * 64;
    int m0 = ((local >> 3) & 1) * 64;
    int k0base = (local >> 4) * 64;         // split-K 8
    const float* A = isK ? g_kv : (g_kv + 512);
    const float* B = isK ? wq : wo;
    int tx = tid & 15, ty = tid >> 4;

    float acc[4][4];
    #pragma unroll
    for (int i = 0; i < 4; i++)
        #pragma unroll
        for (int j = 0; j < 4; j++) acc[i][j] = 0.f;

    for (int k0 = k0base; k0 < k0base + 64; k0 += 16) {
        {
            int mm = tid >> 2, kb = (tid & 3) << 2;
            float4 av = *(const float4*)&A[(size_t)(m0 + mm) * 1024 + k0 + kb];
            As[kb+0][mm] = av.x; As[kb+1][mm] = av.y;
            As[kb+2][mm] = av.z; As[kb+3][mm] = av.w;
        }
        if (isK) {            // B = wq: Bs[k][n] = B[k*512 + n]
            int kk = tid >> 4, nb = (tid & 15) << 2;
            float4 bv = *(const float4*)&B[(size_t)(k0 + kk) * 512 + n0 + nb];
            *(float4*)&Bs[kk][nb] = bv;
        } else {              // B = wo^T
            int nn = tid >> 2, kb = (tid & 3) << 2;
            float4 bv = *(const float4*)&B[(size_t)(n0 + nn) * 512 + k0 + kb];
            Bs[kb+0][nn] = bv.x; Bs[kb+1][nn] = bv.y;
            Bs[kb+2][nn] = bv.z; Bs[kb+3][nn] = bv.w;
        }
        __syncthreads();
        #pragma unroll
        for (int kk = 0; kk < 16; kk++) {
            float4 a4 = *(const float4*)&As[kk][ty << 2];
            float4 b4 = *(const float4*)&Bs[kk][tx << 2];
            float a[4] = {a4.x, a4.y, a4.z, a4.w};
            float bb[4] = {b4.x, b4.y, b4.z, b4.w};
            #pragma unroll
            for (int i = 0; i < 4; i++)
                #pragma unroll
                for (int j = 0; j < 4; j++)
                    acc[i][j] += a[i] * bb[j];
        }
        __syncthreads();
    }
    #pragma unroll
    for (int i = 0; i < 4; i++)
        #pragma unroll
        for (int j = 0; j < 4; j++) {
            int m = m0 + (ty << 2) + i, n = n0 + (tx << 2) + j;
            if (isK) atomicAdd(&g_kpT[(size_t)n * 128 + m], acc[i][j]);
            else     atomicAdd(&g_vp [(size_t)m * 512 + n], acc[i][j]);
        }
}

// ---------------- cvt: fp32 k'/v' -> mma-fragment-order bf16x2 (Round-12 exact) ----------------
__global__ void cvt_kernel() {
    int j = blockIdx.x * 256 + threadIdx.x;   // 0..32767
    if (j < 16384) {          // score B frags: [b][st][k8][lane]
        int lane = j & 31;
        int k8   = (j >> 5) & 31;
        int st   = (j >> 10) & 7;
        int b    = (j >> 13) & 1;
        int tig = lane & 3, grp = lane >> 2;
        int scol = b * 64 + st * 8 + grp;
        int c00 = k8 * 16 + tig * 2;
        int c10 = c00 + 8;
        uint2 r;
        r.x = packbf(g_kpT[(size_t)c00 * 128 + scol], g_kpT[(size_t)(c00+1) * 128 + scol]);
        r.y = packbf(g_kpT[(size_t)c10 * 128 + scol], g_kpT[(size_t)(c10+1) * 128 + scol]);
        g_kf[j] = r;
    } else {                  // combine B frags: [b][k8s][ct][lane]
        int j2 = j - 16384;
        int lane = j2 & 31;
        int ct   = (j2 >> 5) & 63;
        int k8s  = (j2 >> 11) & 3;
        int b    = (j2 >> 13) & 1;
        int tig = lane & 3, grp = lane >> 2;
        int c = ct * 8 + grp;
        int srow = b * 64 + k8s * 16 + tig * 2;
        uint2 r;
        r.x = packbf(g_vp[(size_t)srow     * 512 + c], g_vp[(size_t)(srow+1) * 512 + c]);
        r.y = packbf(g_vp[(size_t)(srow+8) * 512 + c], g_vp[(size_t)(srow+9) * 512 + c]);
        g_vf[j2] = r;
    }
}

// ---------------- fused normalize + attention (bf16 mma, B frags from global) ----------------
// Round-12 exact. block per (b, t, 32-hw tile); 256 threads (8 warps)
__global__ void __launch_bounds__(256) attn_kernel(
    const float* __restrict__ x, const float* __restrict__ gamma,
    const float* __restrict__ beta, const float* __restrict__ bo,
    float* __restrict__ out) {
    extern __shared__ uint shu[];
    float* s_scl  = (float*)shu;                     // 512
    float* s_bia  = (float*)(shu + 512);             // 512
    uint*  frag_h = shu + 1024;                      // 8192: [qw(2)][k8(32)][lane(32)][reg(4)]
    float* sh_sf  = (float*)(shu + 1024 + 8192);     // 32 x SSTR fp32 scores
    uint*  sw_u   = shu + 1024 + 8192 + 32*SSTR;     // 32 x WST packed weights
    __shared__ float sksb[64];

    int bi = blockIdx.x;
    int tile = bi & 31, t = 15 - ((bi >> 5) & 15), b = bi >> 9;
    int hw0 = tile * 32;
    int tid = threadIdx.x;
    const int L   = (t + 1) * 4;
    const int L16 = (L + 15) & ~15;

    // ---- per-block norm params + score bias ----
    if (tid < 64) sksb[tid] = g_ksb[b * 64 + tid];
    #pragma unroll
    for (int c = tid; c < 512; c += 256) {
        int g = c >> 4;
        float mu = g_mu  [b * 512 + g * 16 + t];
        float rs = g_rstd[b * 512 + g * 16 + t];
        float sc = rs * gamma[c];
        s_scl[c] = sc;
        s_bia[c] = beta[c] - mu * sc;
    }
    __syncthreads();

    // ---- stage normalized h into fragment-major layout ----
    #pragma unroll
    for (int it = 0; it < 8; it++) {
        int lin = it * 256 + tid;            // 0..2047
        int cpair = lin >> 3;                // 0..255
        int hwq = (lin & 7) << 2;            // 0,4,..,28
        int c0 = cpair * 2;
        const float* xp = x + ((size_t)(b * 512 + c0) * 16 + t) * 1024 + hw0 + hwq;
        float4 x0 = *(const float4*)xp;
        float4 x1 = *(const float4*)(xp + 16384);    // c0+1 row
        float sc0 = s_scl[c0],   bi0 = s_bia[c0];
        float sc1 = s_scl[c0+1], bi1 = s_bia[c0+1];
        int k8 = cpair >> 3;
        int cp7 = cpair & 7;
        int tig_ = cp7 & 3;
        int regc = (cp7 >> 2) << 1;          // 0 or 2
        float xa[4] = {x0.x, x0.y, x0.z, x0.w};
        float xb[4] = {x1.x, x1.y, x1.z, x1.w};
        #pragma unroll
        for (int i = 0; i < 4; i++) {
            int hw = hwq + i;
            int qw = hw >> 4, r = hw & 15;
            int lane2 = (r & 7) * 4 + tig_;
            int reg = regc + (r >> 3);
            frag_h[(qw * 32 + k8) * 128 + lane2 * 4 + reg] =
                packbf(xa[i] * sc0 + bi0, xb[i] * sc1 + bi1);
        }
    }
    __syncthreads();

    int warp = tid >> 5, lane = tid & 31;
    int grp = lane >> 2, tig = lane & 3;

    // ================= scores: warp = one s-tile (8 s), both q-tiles =================
    {
        int st = warp;
        if (st * 8 < L) {
            float4 C0 = {0,0,0,0}, C1 = {0,0,0,0};
            const uint2* kf = g_kf + ((size_t)(b * 8 + st) * 32) * 32 + lane;
            #pragma unroll 8
            for (int k8 = 0; k8 < 32; k8++) {
                uint4 A0 = *(const uint4*)&frag_h[k8 * 128 + lane * 4];
                uint4 A1 = *(const uint4*)&frag_h[(32 + k8) * 128 + lane * 4];
                uint2 Bv = kf[k8 * 32];
                mma_bf16(C0, A0.x, A0.y, A0.z, A0.w, Bv.x, Bv.y);
                mma_bf16(C1, A1.x, A1.y, A1.z, A1.w, Bv.x, Bv.y);
            }
            int s = st * 8 + 2 * tig;
            if (s < L) {
                float kb = sksb[s];
                sh_sf[ grp      * SSTR + s] = (C0.x + kb) * SCALE;
                sh_sf[(grp + 8) * SSTR + s] = (C0.z + kb) * SCALE;
                sh_sf[(16 + grp) * SSTR + s] = (C1.x + kb) * SCALE;
                sh_sf[(24 + grp) * SSTR + s] = (C1.z + kb) * SCALE;
            }
            if (s + 1 < L) {
                float kb = sksb[s + 1];
                sh_sf[ grp      * SSTR + s + 1] = (C0.y + kb) * SCALE;
                sh_sf[(grp + 8) * SSTR + s + 1] = (C0.w + kb) * SCALE;
                sh_sf[(16 + grp) * SSTR + s + 1] = (C1.y + kb) * SCALE;
                sh_sf[(24 + grp) * SSTR + s + 1] = (C1.w + kb) * SCALE;
            }
        }
    }
    __syncthreads();

    // ================= softmax (warp = 4 rows) -> packed bf16x2 weights =================
    for (int r = 0; r < 4; r++) {
        int q = warp * 4 + r;
        float v0 = (lane      < L) ? sh_sf[q * SSTR + lane     ] : -INFINITY;
        float v1 = (lane + 32 < L) ? sh_sf[q * SSTR + lane + 32] : -INFINITY;
        float mx = fmaxf(v0, v1);
        #pragma unroll
        for (int off = 16; off > 0; off >>= 1) mx = fmaxf(mx, __shfl_xor_sync(FULLMASK, mx, off));
        float e0 = __expf(v0 - mx), e1 = __expf(v1 - mx);
        float ds = e0 + e1;
        #pragma unroll
        for (int off = 16; off > 0; off >>= 1) ds += __shfl_xor_sync(FULLMASK, ds, off);
        float inv = 1.f / ds;
        float we = e0 * inv, wo_ = e1 * inv;     // s=lane, s=lane+32 (0 beyond L)
        int i0 = (2 * lane) & 31, i1 = (2 * lane + 1) & 31;
        float alo = __shfl_sync(FULLMASK, we,  i0), blo = __shfl_sync(FULLMASK, we,  i1);
        float ahi = __shfl_sync(FULLMASK, wo_, i0), bhi = __shfl_sync(FULLMASK, wo_, i1);
        float wa = lane < 16 ? alo : ahi;
        float wb = lane < 16 ? blo : bhi;
        sw_u[q * WST + lane] = packbf(wa, wb);
    }
    __syncthreads();

    // ================= combine: warp owns 64 c cols, both q-tiles; fused epilogue =================
    {
        const int kmax = L16 >> 4;
        int w = warp;
        #pragma unroll
        for (int ch2 = 0; ch2 < 2; ch2++) {
            float4 D0[4], D1[4];
            #pragma unroll
            for (int nt = 0; nt < 4; nt++) {
                D0[nt] = make_float4(0.f, 0.f, 0.f, 0.f);
                D1[nt] = make_float4(0.f, 0.f, 0.f, 0.f);
            }
            for (int k8s = 0; k8s < kmax; k8s++) {
                int sp = k8s * 8;
                uint a00 = sw_u[ grp       * WST + sp + tig];
                uint a01 = sw_u[(grp + 8)  * WST + sp + tig];
                uint a02 = sw_u[ grp       * WST + sp + tig + 4];
                uint a03 = sw_u[(grp + 8)  * WST + sp + tig + 4];
                uint a10 = sw_u[(16 + grp) * WST + sp + tig];
                uint a11 = sw_u[(24 + grp) * WST + sp + tig];
                uint a12 = sw_u[(16 + grp) * WST + sp + tig + 4];
                uint a13 = sw_u[(24 + grp) * WST + sp + tig + 4];
                #pragma unroll
                for (int nt = 0; nt < 4; nt++) {
                    int ct = w * 8 + ch2 * 4 + nt;
                    uint2 Bv = g_vf[((size_t)(b * 4 + k8s) * 64 + ct) * 32 + lane];
                    mma_bf16(D0[nt], a00, a01, a02, a03, Bv.x, Bv.y);
                    mma_bf16(D1[nt], a10, a11, a12, a13, Bv.x, Bv.y);
                }
            }
            // fused epilogue: out = x + o + bo
            #pragma unroll
            for (int nt = 0; nt < 4; nt++) {
                int ct = w * 8 + ch2 * 4 + nt;
                int c0 = ct * 8 + 2 * tig;
                float bo0 = bo[c0], bo1 = bo[c0 + 1];
                size_t gA0 = ((size_t)(b * 512 + c0) * 16 + t) * 1024 + hw0 + grp;
                size_t gA1 = gA0 + 16384;     // c0+1 row
                out[gA0]      = x[gA0]      + D0[nt].x + bo0;
                out[gA1]      = x[gA1]      + D0[nt].y + bo1;
                out[gA0 + 8]  = x[gA0 + 8]  + D0[nt].z + bo0;
                out[gA1 + 8]  = x[gA1 + 8]  + D0[nt].w + bo1;
                size_t gB0 = gA0 + 16;        // q-tile 1: hw +16
                size_t gB1 = gA1 + 16;
                out[gB0]      = x[gB0]      + D1[nt].x + bo0;
                out[gB1]      = x[gB1]      + D1[nt].y + bo1;
                out[gB0 + 8]  = x[gB0 + 8]  + D1[nt].z + bo0;
                out[gB1 + 8]  = x[gB1 + 8]  + D1[nt].w + bo1;
            }
        }
    }
}

// ---------------- launch ----------------
extern "C" void kernel_launch(void* const* d_in, const int* in_sizes, int n_in,
                              void* d_out, int out_size) {
    const float* x       = (const float*)d_in[0];
    const float* context = (const float*)d_in[1];
    const float* gamma   = (const float*)d_in[2];
    const float* beta    = (const float*)d_in[3];
    const float* wq      = (const float*)d_in[4];
    const float* bq      = (const float*)d_in[5];
    const float* wkv     = (const float*)d_in[6];
    const float* bkv     = (const float*)d_in[7];
    const float* wo      = (const float*)d_in[8];
    const float* bo      = (const float*)d_in[9];
    float* out = (float*)d_out;

    const int SMEM_BYTES = (1024 + 8192 + 32*SSTR + 32*WST) * 4;   // 50176
    cudaFuncSetAttribute(attn_kernel, cudaFuncAttributeMaxDynamicSharedMemorySize, SMEM_BYTES);

    seed_kernel<<<256, 256>>>(bkv);
    kv_kernel<<<256, 256>>>(context, wkv);
    mid_kernel<<<1284, 256>>>(x, wq, wo, bq);   // proj2 + ksb + gn stats (concurrent)
    cvt_kernel<<<128, 256>>>();
    attn_kernel<<<Bz * Tt * 32, 256, SMEM_BYTES>>>(x, gamma, beta, bo, out);
}

// round 16
// speedup vs baseline: 1.1373x; 1.0339x over previous
#include <cuda_runtime.h>
#include <cuda_bf16.h>
#include <math.h>

#define Bz   2
#define Cc   512
#define Tt   16
#define HWp  1024
#define EPS  1e-5f
#define SCALE 0.04419417382415922f  // 512^-0.5
#define FULLMASK 0xffffffffu
#define SSTR 68     // fp32 score row stride
#define WST  36     // packed weight row stride (uints)

typedef unsigned int uint;

// ---------------- helpers ----------------
__device__ __forceinline__ uint packbf(float lo, float hi) {
    uint r; asm("cvt.rn.bf16x2.f32 %0, %1, %2;" : "=r"(r) : "f"(hi), "f"(lo)); return r;
}
__device__ __forceinline__ void mma_bf16(float4& d, uint a0, uint a1, uint a2, uint a3,
                                         uint b0, uint b1) {
    asm volatile("mma.sync.aligned.m16n8k16.row.col.f32.bf16.bf16.f32 "
                 "{%0,%1,%2,%3}, {%4,%5,%6,%7}, {%8,%9}, {%0,%1,%2,%3};"
                 : "+f"(d.x), "+f"(d.y), "+f"(d.z), "+f"(d.w)
                 : "r"(a0), "r"(a1), "r"(a2), "r"(a3), "r"(b0), "r"(b1));
}

// ---------------- scratch ----------------
__device__ float  g_mu  [Bz * 32 * Tt];
__device__ float  g_rstd[Bz * 32 * Tt];
__device__ float  g_kv  [128 * 1024];     // [b*64+s][2C]
__device__ float  g_kpT [512 * 128];      // fp32 [c][b*64+s]
__device__ float  g_vp  [128 * 512];      // fp32 [b*64+s][c]
__device__ uint2  g_kf  [16384];          // score B frags bf16x2: [b][st(8)][k8(32)][lane(32)]
__device__ uint2  g_vf  [16384];          // combine B frags bf16x2: [b][k8s(4)][ct(64)][lane(32)]
__device__ float  g_ksb [128];

// ---------------- seed: g_kv = bkv bcast, g_kpT = 0, g_vp = 0 ----------------
__global__ void seed_kernel(const float* __restrict__ bkv) {
    int i4 = (blockIdx.x * 256 + threadIdx.x) * 4;   // 0..262140
    if (i4 < 131072) {
        float4 bv = *(const float4*)&bkv[i4 & 1023];
        *(float4*)&g_kv[i4] = bv;
    } else if (i4 < 196608) {
        *(float4*)&g_kpT[i4 - 131072] = make_float4(0.f, 0.f, 0.f, 0.f);
    } else {
        *(float4*)&g_vp[i4 - 196608] = make_float4(0.f, 0.f, 0.f, 0.f);
    }
}

// ---------------- kv = context @ wkv^T (split-K 8, atomic) ----------------
__global__ void kv_kernel(const float* __restrict__ context, const float* __restrict__ wkv) {
    int bid = blockIdx.x;
    int tid = threadIdx.x;
    __shared__ float As[16][68];
    __shared__ float Bs[16][68];
    int n0 = (bid & 15) * 64;
    int m0 = ((bid >> 4) & 1) * 64;
    int k0base = (bid >> 5) * 128;
    int tx = tid & 15, ty = tid >> 4;

    float acc[4][4];
    #pragma unroll
    for (int i = 0; i < 4; i++)
        #pragma unroll
        for (int j = 0; j < 4; j++) acc[i][j] = 0.f;

    for (int k0 = k0base; k0 < k0base + 128; k0 += 16) {
        {
            int mm = tid >> 2, kb = (tid & 3) << 2;
            float4 av = *(const float4*)&context[(size_t)(m0 + mm) * 1024 + k0 + kb];
            As[kb+0][mm] = av.x; As[kb+1][mm] = av.y;
            As[kb+2][mm] = av.z; As[kb+3][mm] = av.w;
        }
        {
            int nn = tid >> 2, kb = (tid & 3) << 2;
            float4 bv = *(const float4*)&wkv[(size_t)(n0 + nn) * 1024 + k0 + kb];
            Bs[kb+0][nn] = bv.x; Bs[kb+1][nn] = bv.y;
            Bs[kb+2][nn] = bv.z; Bs[kb+3][nn] = bv.w;
        }
        __syncthreads();
        #pragma unroll
        for (int kk = 0; kk < 16; kk++) {
            float4 a4 = *(const float4*)&As[kk][ty << 2];
            float4 b4 = *(const float4*)&Bs[kk][tx << 2];
            float a[4] = {a4.x, a4.y, a4.z, a4.w};
            float bb[4] = {b4.x, b4.y, b4.z, b4.w};
            #pragma unroll
            for (int i = 0; i < 4; i++)
                #pragma unroll
                for (int j = 0; j < 4; j++)
                    acc[i][j] += a[i] * bb[j];
        }
        __syncthreads();
    }
    #pragma unroll
    for (int i = 0; i < 4; i++)
        #pragma unroll
        for (int j = 0; j < 4; j++)
            atomicAdd(&g_kv[(size_t)(m0 + (ty<<2) + i) * 1024 + n0 + (tx<<2) + j], acc[i][j]);
}

// ---------------- mid: kT (0-127), vp (128-255), ksb (256-259), gn stats (260-1283) ----------------
__global__ void mid_kernel(const float* __restrict__ x, const float* __restrict__ wq,
                           const float* __restrict__ wo, const float* __restrict__ bq) {
    int bid = blockIdx.x;
    int tid = threadIdx.x;

    if (bid >= 260) {     // ---- groupnorm stats (independent of kv) ----
        int idx = bid - 260;                 // b*512 + g*16 + t
        int b = idx >> 9, g = (idx >> 4) & 31, t = idx & 15;
        float s = 0.f, sq = 0.f;
        for (int ci = 0; ci < 16; ci++) {
            const float4* row = (const float4*)(x + (size_t)(((b*Cc + g*16 + ci)*Tt + t)) * HWp);
            float4 v = row[tid];
            s  += v.x + v.y + v.z + v.w;
            sq += v.x*v.x + v.y*v.y + v.z*v.z + v.w*v.w;
        }
        __shared__ float s1[256], s2[256];
        s1[tid] = s; s2[tid] = sq;
        __syncthreads();
        for (int st = 128; st > 0; st >>= 1) {
            if (tid < st) { s1[tid] += s1[tid + st]; s2[tid] += s2[tid + st]; }
            __syncthreads();
        }
        if (tid == 0) {
            const float invN = 1.f / 16384.f;
            float mu  = s1[0] * invN;
            float var = s2[0] * invN - mu * mu;
            g_mu[idx] = mu;
            g_rstd[idx] = rsqrtf(var + EPS);
        }
        return;
    }

    if (bid >= 256) {         // ksb: bq . k
        int warp = tid >> 5, lane = tid & 31;
        int base = (bid - 256) * 32 + warp * 4;
        for (int r = 0; r < 4; r++) {
            int row = base + r;
            const float4* kr = (const float4*)&g_kv[(size_t)row * 1024];
            float s = 0.f;
            #pragma unroll
            for (int i = 0; i < 4; i++) {
                float4 kvv = kr[i*32 + lane];
                float4 bqv = *(const float4*)&bq[(i*32 + lane) << 2];
                s += kvv.x*bqv.x + kvv.y*bqv.y + kvv.z*bqv.z + kvv.w*bqv.w;
            }
            #pragma unroll
            for (int off = 16; off > 0; off >>= 1) s += __shfl_xor_sync(FULLMASK, s, off);
            if (lane == 0) g_ksb[row] = s;
        }
        return;
    }

    __shared__ float As[16][68];
    __shared__ float Bs[16][68];
    bool isK = bid < 128;
    int local = bid & 127;
    int n0 = (local & 7) * 64;
    int m0 = ((local >> 3) & 1) * 64;
    int k0base = (local >> 4) * 64;         // split-K 8
    const float* A = isK ? g_kv : (g_kv + 512);
    const float* B = isK ? wq : wo;
    int tx = tid & 15, ty = tid >> 4;

    float acc[4][4];
    #pragma unroll
    for (int i = 0; i < 4; i++)
        #pragma unroll
        for (int j = 0; j < 4; j++) acc[i][j] = 0.f;

    for (int k0 = k0base; k0 < k0base + 64; k0 += 16) {
        {
            int mm = tid >> 2, kb = (tid & 3) << 2;
            float4 av = *(const float4*)&A[(size_t)(m0 + mm) * 1024 + k0 + kb];
            As[kb+0][mm] = av.x; As[kb+1][mm] = av.y;
            As[kb+2][mm] = av.z; As[kb+3][mm] = av.w;
        }
        if (isK) {            // B = wq: Bs[k][n] = B[k*512 + n]
            int kk = tid >> 4, nb = (tid & 15) << 2;
            float4 bv = *(const float4*)&B[(size_t)(k0 + kk) * 512 + n0 + nb];
            *(float4*)&Bs[kk][nb] = bv;
        } else {              // B = wo^T
            int nn = tid >> 2, kb = (tid & 3) << 2;
            float4 bv = *(const float4*)&B[(size_t)(n0 + nn) * 512 + k0 + kb];
            Bs[kb+0][nn] = bv.x; Bs[kb+1][nn] = bv.y;
            Bs[kb+2][nn] = bv.z; Bs[kb+3][nn] = bv.w;
        }
        __syncthreads();
        #pragma unroll
        for (int kk = 0; kk < 16; kk++) {
            float4 a4 = *(const float4*)&As[kk][ty << 2];
            float4 b4 = *(const float4*)&Bs[kk][tx << 2];
            float a[4] = {a4.x, a4.y, a4.z, a4.w};
            float bb[4] = {b4.x, b4.y, b4.z, b4.w};
            #pragma unroll
            for (int i = 0; i < 4; i++)
                #pragma unroll
                for (int j = 0; j < 4; j++)
                    acc[i][j] += a[i] * bb[j];
        }
        __syncthreads();
    }
    #pragma unroll
    for (int i = 0; i < 4; i++)
        #pragma unroll
        for (int j = 0; j < 4; j++) {
            int m = m0 + (ty << 2) + i, n = n0 + (tx << 2) + j;
            if (isK) atomicAdd(&g_kpT[(size_t)n * 128 + m], acc[i][j]);
            else     atomicAdd(&g_vp [(size_t)m * 512 + n], acc[i][j]);
        }
}

// ---------------- cvt: fp32 k'/v' -> mma-fragment-order bf16x2 ----------------
__global__ void cvt_kernel() {
    int j = blockIdx.x * 256 + threadIdx.x;   // 0..32767
    if (j < 16384) {          // score B frags: [b][st][k8][lane]
        int lane = j & 31;
        int k8   = (j >> 5) & 31;
        int st   = (j >> 10) & 7;
        int b    = (j >> 13) & 1;
        int tig = lane & 3, grp = lane >> 2;
        int scol = b * 64 + st * 8 + grp;
        int c00 = k8 * 16 + tig * 2;
        int c10 = c00 + 8;
        uint2 r;
        r.x = packbf(g_kpT[(size_t)c00 * 128 + scol], g_kpT[(size_t)(c00+1) * 128 + scol]);
        r.y = packbf(g_kpT[(size_t)c10 * 128 + scol], g_kpT[(size_t)(c10+1) * 128 + scol]);
        g_kf[j] = r;
    } else {                  // combine B frags: [b][k8s][ct][lane]
        int j2 = j - 16384;
        int lane = j2 & 31;
        int ct   = (j2 >> 5) & 63;
        int k8s  = (j2 >> 11) & 3;
        int b    = (j2 >> 13) & 1;
        int tig = lane & 3, grp = lane >> 2;
        int c = ct * 8 + grp;
        int srow = b * 64 + k8s * 16 + tig * 2;
        uint2 r;
        r.x = packbf(g_vp[(size_t)srow     * 512 + c], g_vp[(size_t)(srow+1) * 512 + c]);
        r.y = packbf(g_vp[(size_t)(srow+8) * 512 + c], g_vp[(size_t)(srow+9) * 512 + c]);
        g_vf[j2] = r;
    }
}

// ---------------- fused normalize + attention (bf16 mma) + coalesced epilogue ----------------
// block per (b, t, 32-hw tile); 256 threads (8 warps)
__global__ void __launch_bounds__(256) attn_kernel(
    const float* __restrict__ x, const float* __restrict__ gamma,
    const float* __restrict__ beta, const float* __restrict__ bo,
    float* __restrict__ out) {
    extern __shared__ uint shu[];
    float* s_scl  = (float*)shu;                     // 512 (scl, later bo)
    float* s_bia  = (float*)(shu + 512);             // 512
    uint*  frag_h = shu + 1024;                      // 8192: [qw(2)][k8(32)][lane(32)][reg(4)]
    float* st_o   = (float*)(shu + 1024);            // epilogue staging 256x36 (overlays frag_h+sh_sf)
    float* sh_sf  = (float*)(shu + 1024 + 8192);     // 32 x SSTR fp32 scores
    uint*  sw_u   = shu + 1024 + 8192 + 32*SSTR;     // 32 x WST packed weights
    __shared__ float sksb[64];

    int bi = blockIdx.x;
    int tile = bi & 31, t = 15 - ((bi >> 5) & 15), b = bi >> 9;
    int hw0 = tile * 32;
    int tid = threadIdx.x;
    const int L   = (t + 1) * 4;
    const int L16 = (L + 15) & ~15;

    // ---- per-block norm params + score bias ----
    if (tid < 64) sksb[tid] = g_ksb[b * 64 + tid];
    #pragma unroll
    for (int c = tid; c < 512; c += 256) {
        int g = c >> 4;
        float mu = g_mu  [b * 512 + g * 16 + t];
        float rs = g_rstd[b * 512 + g * 16 + t];
        float sc = rs * gamma[c];
        s_scl[c] = sc;
        s_bia[c] = beta[c] - mu * sc;
    }
    __syncthreads();

    // ---- stage normalized h into fragment-major layout ----
    #pragma unroll
    for (int it = 0; it < 8; it++) {
        int lin = it * 256 + tid;            // 0..2047
        int cpair = lin >> 3;                // 0..255
        int hwq = (lin & 7) << 2;            // 0,4,..,28
        int c0 = cpair * 2;
        const float* xp = x + ((size_t)(b * 512 + c0) * 16 + t) * 1024 + hw0 + hwq;
        float4 x0 = *(const float4*)xp;
        float4 x1 = *(const float4*)(xp + 16384);    // c0+1 row
        float sc0 = s_scl[c0],   bi0 = s_bia[c0];
        float sc1 = s_scl[c0+1], bi1 = s_bia[c0+1];
        int k8 = cpair >> 3;
        int cp7 = cpair & 7;
        int tig_ = cp7 & 3;
        int regc = (cp7 >> 2) << 1;          // 0 or 2
        float xa[4] = {x0.x, x0.y, x0.z, x0.w};
        float xb[4] = {x1.x, x1.y, x1.z, x1.w};
        #pragma unroll
        for (int i = 0; i < 4; i++) {
            int hw = hwq + i;
            int qw = hw >> 4, r = hw & 15;
            int lane2 = (r & 7) * 4 + tig_;
            int reg = regc + (r >> 3);
            frag_h[(qw * 32 + k8) * 128 + lane2 * 4 + reg] =
                packbf(xa[i] * sc0 + bi0, xb[i] * sc1 + bi1);
        }
    }
    __syncthreads();

    int warp = tid >> 5, lane = tid & 31;
    int grp = lane >> 2, tig = lane & 3;

    // ================= scores: warp = one s-tile (8 s), both q-tiles =================
    {
        int st = warp;
        if (st * 8 < L) {
            float4 C0 = {0,0,0,0}, C1 = {0,0,0,0};
            const uint2* kf = g_kf + ((size_t)(b * 8 + st) * 32) * 32 + lane;
            #pragma unroll 8
            for (int k8 = 0; k8 < 32; k8++) {
                uint4 A0 = *(const uint4*)&frag_h[k8 * 128 + lane * 4];
                uint4 A1 = *(const uint4*)&frag_h[(32 + k8) * 128 + lane * 4];
                uint2 Bv = kf[k8 * 32];
                mma_bf16(C0, A0.x, A0.y, A0.z, A0.w, Bv.x, Bv.y);
                mma_bf16(C1, A1.x, A1.y, A1.z, A1.w, Bv.x, Bv.y);
            }
            int s = st * 8 + 2 * tig;
            if (s < L) {
                float kb = sksb[s];
                sh_sf[ grp      * SSTR + s] = (C0.x + kb) * SCALE;
                sh_sf[(grp + 8) * SSTR + s] = (C0.z + kb) * SCALE;
                sh_sf[(16 + grp) * SSTR + s] = (C1.x + kb) * SCALE;
                sh_sf[(24 + grp) * SSTR + s] = (C1.z + kb) * SCALE;
            }
            if (s + 1 < L) {
                float kb = sksb[s + 1];
                sh_sf[ grp      * SSTR + s + 1] = (C0.y + kb) * SCALE;
                sh_sf[(grp + 8) * SSTR + s + 1] = (C0.w + kb) * SCALE;
                sh_sf[(16 + grp) * SSTR + s + 1] = (C1.y + kb) * SCALE;
                sh_sf[(24 + grp) * SSTR + s + 1] = (C1.w + kb) * SCALE;
            }
        }
    }
    __syncthreads();

    // ================= softmax (warp = 4 rows) -> packed bf16x2 weights =================
    for (int r = 0; r < 4; r++) {
        int q = warp * 4 + r;
        float v0 = (lane      < L) ? sh_sf[q * SSTR + lane     ] : -INFINITY;
        float v1 = (lane + 32 < L) ? sh_sf[q * SSTR + lane + 32] : -INFINITY;
        float mx = fmaxf(v0, v1);
        #pragma unroll
        for (int off = 16; off > 0; off >>= 1) mx = fmaxf(mx, __shfl_xor_sync(FULLMASK, mx, off));
        float e0 = __expf(v0 - mx), e1 = __expf(v1 - mx);
        float ds = e0 + e1;
        #pragma unroll
        for (int off = 16; off > 0; off >>= 1) ds += __shfl_xor_sync(FULLMASK, ds, off);
        float inv = 1.f / ds;
        float we = e0 * inv, wo_ = e1 * inv;     // s=lane, s=lane+32 (0 beyond L)
        int i0 = (2 * lane) & 31, i1 = (2 * lane + 1) & 31;
        float alo = __shfl_sync(FULLMASK, we,  i0), blo = __shfl_sync(FULLMASK, we,  i1);
        float ahi = __shfl_sync(FULLMASK, wo_, i0), bhi = __shfl_sync(FULLMASK, wo_, i1);
        float wa = lane < 16 ? alo : ahi;
        float wb = lane < 16 ? blo : bhi;
        sw_u[q * WST + lane] = packbf(wa, wb);
    }
    // preload bo into dead s_scl region (scl consumed during h staging)
    s_scl[tid]       = bo[tid];
    s_scl[tid + 256] = bo[tid + 256];
    __syncthreads();

    // ================= combine: warp owns 64 c cols, both q-tiles; staged epilogue =================
    {
        const int kmax = L16 >> 4;
        int w = warp;
        #pragma unroll
        for (int ch2 = 0; ch2 < 2; ch2++) {
            float4 D0[4], D1[4];
            #pragma unroll
            for (int nt = 0; nt < 4; nt++) {
                D0[nt] = make_float4(0.f, 0.f, 0.f, 0.f);
                D1[nt] = make_float4(0.f, 0.f, 0.f, 0.f);
            }
            for (int k8s = 0; k8s < kmax; k8s++) {
                int sp = k8s * 8;
                uint a00 = sw_u[ grp       * WST + sp + tig];
                uint a01 = sw_u[(grp + 8)  * WST + sp + tig];
                uint a02 = sw_u[ grp       * WST + sp + tig + 4];
                uint a03 = sw_u[(grp + 8)  * WST + sp + tig + 4];
                uint a10 = sw_u[(16 + grp) * WST + sp + tig];
                uint a11 = sw_u[(24 + grp) * WST + sp + tig];
                uint a12 = sw_u[(16 + grp) * WST + sp + tig + 4];
                uint a13 = sw_u[(24 + grp) * WST + sp + tig + 4];
                #pragma unroll
                for (int nt = 0; nt < 4; nt++) {
                    int ct = w * 8 + ch2 * 4 + nt;
                    uint2 Bv = g_vf[((size_t)(b * 4 + k8s) * 64 + ct) * 32 + lane];
                    mma_bf16(D0[nt], a00, a01, a02, a03, Bv.x, Bv.y);
                    mma_bf16(D1[nt], a10, a11, a12, a13, Bv.x, Bv.y);
                }
            }
            // stage D fragments into [cidx][hw] smem (stride 36 -> conflict-free)
            #pragma unroll
            for (int nt = 0; nt < 4; nt++) {
                int cidx = w * 32 + nt * 8 + 2 * tig;   // c = (cidx>>5)*64 + ch2*32 + (cidx&31)
                st_o[ cidx      * 36 + grp     ] = D0[nt].x;
                st_o[(cidx + 1) * 36 + grp     ] = D0[nt].y;
                st_o[ cidx      * 36 + grp + 8 ] = D0[nt].z;
                st_o[(cidx + 1) * 36 + grp + 8 ] = D0[nt].w;
                st_o[ cidx      * 36 + grp + 16] = D1[nt].x;
                st_o[(cidx + 1) * 36 + grp + 16] = D1[nt].y;
                st_o[ cidx      * 36 + grp + 24] = D1[nt].z;
                st_o[(cidx + 1) * 36 + grp + 24] = D1[nt].w;
            }
            __syncthreads();
            // coalesced writeout: warp per channel-row, 128B lines
            #pragma unroll 4
            for (int it = 0; it < 32; it++) {
                int row = it * 8 + w;                    // cidx 0..255
                int c = ((row >> 5) << 6) + ch2 * 32 + (row & 31);
                float val = st_o[row * 36 + lane];
                size_t g = ((size_t)(b * 512 + c) * 16 + t) * 1024 + hw0 + lane;
                out[g] = x[g] + val + s_scl[c];
            }
            __syncthreads();
        }
    }
}

// ---------------- launch ----------------
extern "C" void kernel_launch(void* const* d_in, const int* in_sizes, int n_in,
                              void* d_out, int out_size) {
    const float* x       = (const float*)d_in[0];
    const float* context = (const float*)d_in[1];
    const float* gamma   = (const float*)d_in[2];
    const float* beta    = (const float*)d_in[3];
    const float* wq      = (const float*)d_in[4];
    const float* bq      = (const float*)d_in[5];
    const float* wkv     = (const float*)d_in[6];
    const float* bkv     = (const float*)d_in[7];
    const float* wo      = (const float*)d_in[8];
    const float* bo      = (const float*)d_in[9];
    float* out = (float*)d_out;

    const int SMEM_BYTES = (1024 + 8192 + 32*SSTR + 32*WST) * 4;   // 50176 (staging overlays)
    cudaFuncSetAttribute(attn_kernel, cudaFuncAttributeMaxDynamicSharedMemorySize, SMEM_BYTES);

    seed_kernel<<<256, 256>>>(bkv);
    kv_kernel<<<256, 256>>>(context, wkv);
    mid_kernel<<<1284, 256>>>(x, wq, wo, bq);   // proj2 + ksb + gn stats (concurrent)
    cvt_kernel<<<128, 256>>>();
    attn_kernel<<<Bz * Tt * 32, 256, SMEM_BYTES>>>(x, gamma, beta, bo, out);
}